// round 1
// baseline (speedup 1.0000x reference)
#include <cuda_runtime.h>
#include <cstdint>

// seir_base: out[n,i,o] = relu( sum_c (sum_j A[i,j]*Ap[n,i,j]*x[n,j,c]) * fc_w[o,c] + fc_b[o] )
// N = 1e6 regions, 5 states, 32 channels. fp32 throughout.
//
// Strategy: warp-per-region, lane = channel. Packed f32x2 FMA for the 32x32 fc.

#define FULL_MASK 0xffffffffu

__device__ __forceinline__ unsigned long long pk(float lo, float hi) {
    unsigned long long r;
    asm("mov.b64 %0, {%1, %2};" : "=l"(r) : "f"(lo), "f"(hi));
    return r;
}
__device__ __forceinline__ void upk(unsigned long long v, float& lo, float& hi) {
    asm("mov.b64 {%0, %1}, %2;" : "=f"(lo), "=f"(hi) : "l"(v));
}
__device__ __forceinline__ unsigned long long fma2(unsigned long long a,
                                                   unsigned long long b,
                                                   unsigned long long c) {
    unsigned long long d;
    asm("fma.rn.f32x2 %0, %1, %2, %3;" : "=l"(d) : "l"(a), "l"(b), "l"(c));
    return d;
}

constexpr int THREADS = 256;
constexpr int WPB = THREADS / 32;   // warps per block
constexpr int CHUNK = 64;           // regions per warp (contiguous)

__global__ __launch_bounds__(THREADS)
void seir_kernel(const float* __restrict__ A,
                 const float* __restrict__ Ap,
                 const float* __restrict__ x,
                 const float* __restrict__ fcw,
                 const float* __restrict__ fcb,
                 float* __restrict__ out,
                 int n_regions)
{
    __shared__ float shH[WPB][5 * 32];

    const int warp = threadIdx.x >> 5;
    const int lane = threadIdx.x & 31;
    const int gwarp = blockIdx.x * WPB + warp;

    // ---- per-lane persistent state ----
    // A element for this lane's (i,j) slot (lanes 0..24)
    const float a_l = (lane < 25) ? A[lane] : 0.0f;
    // fc_w row `lane` packed as 16 f32x2 values
    unsigned long long w2[16];
    {
        const float2* fw = reinterpret_cast<const float2*>(fcw + lane * 32);
#pragma unroll
        for (int k = 0; k < 16; k++) {
            float2 t = fw[k];
            w2[k] = pk(t.x, t.y);
        }
    }
    const float bias = fcb[lane];
    float* hbuf = shH[warp];

    long long n0 = (long long)gwarp * CHUNK;
    long long n1 = n0 + CHUNK;
    if (n1 > n_regions) n1 = n_regions;

    for (long long n = n0; n < n1; n++) {
        // ---- W = A .* Ap : one element per lane (lanes 0..24) ----
        float wv = 0.0f;
        if (lane < 25) wv = a_l * Ap[n * 25 + lane];

        // ---- load x row: lane = channel, 5 coalesced 128B loads ----
        float xj[5];
        const float* xp = x + n * 160 + lane;
#pragma unroll
        for (int j = 0; j < 5; j++) xj[j] = xp[j * 32];

        // ---- h[i] = sum_j W[i][j] * x[j][lane]  (W via warp shuffle) ----
        float h[5];
#pragma unroll
        for (int i = 0; i < 5; i++) {
            float acc = __shfl_sync(FULL_MASK, wv, i * 5 + 0) * xj[0];
#pragma unroll
            for (int j = 1; j < 5; j++)
                acc = fmaf(__shfl_sync(FULL_MASK, wv, i * 5 + j), xj[j], acc);
            h[i] = acc;
        }

        // ---- stage h to shared for the channel-transpose in fc ----
#pragma unroll
        for (int i = 0; i < 5; i++) hbuf[i * 32 + lane] = h[i];
        __syncwarp();

        // ---- fc: out[i][lane] = relu(bias + sum_c h[i][c] * fc_w[lane][c]) ----
        float* op = out + n * 160 + lane;
#pragma unroll
        for (int i = 0; i < 5; i++) {
            unsigned long long acc2 = pk(bias, 0.0f);
            const float4* hp = reinterpret_cast<const float4*>(hbuf + i * 32);
#pragma unroll
            for (int c4 = 0; c4 < 8; c4++) {
                float4 hv = hp[c4];  // broadcast LDS.128, conflict-free
                acc2 = fma2(pk(hv.x, hv.y), w2[2 * c4 + 0], acc2);
                acc2 = fma2(pk(hv.z, hv.w), w2[2 * c4 + 1], acc2);
            }
            float lo, hi;
            upk(acc2, lo, hi);
            op[i * 32] = fmaxf(lo + hi, 0.0f);
        }
        __syncwarp();  // protect hbuf before next region overwrites it
    }
}

extern "C" void kernel_launch(void* const* d_in, const int* in_sizes, int n_in,
                              void* d_out, int out_size)
{
    const float* A   = (const float*)d_in[0];
    const float* Ap  = (const float*)d_in[1];
    const float* x   = (const float*)d_in[2];
    const float* fcw = (const float*)d_in[3];
    const float* fcb = (const float*)d_in[4];
    float* out = (float*)d_out;

    const int n_regions = in_sizes[1] / 25;

    const long long total_warps = ((long long)n_regions + CHUNK - 1) / CHUNK;
    const int blocks = (int)((total_warps + WPB - 1) / WPB);

    seir_kernel<<<blocks, THREADS>>>(A, Ap, x, fcw, fcb, out, n_regions);
}

// round 2
// speedup vs baseline: 1.4069x; 1.4069x over previous
#include <cuda_runtime.h>
#include <cstdint>

// seir_base: out[n,i,o] = relu( sum_c (sum_j A[i,j]*Ap[n,i,j]*x[n,j,c]) * fc_w[o,c] + fc_b[o] )
// N=1e6 regions, 5 states, 32 channels, fp32.
//
// R2 strategy: h (graph aggregation) in exact fp32 with warp lane=channel;
// fc (5N x 32)@(32x32) GEMM on tensor cores via mma.sync m16n8k8 tf32.

#define FULL_MASK 0xffffffffu

__device__ __forceinline__ uint32_t f2tf32(float f) {
    uint32_t r;
    asm("cvt.rna.tf32.f32 %0, %1;" : "=r"(r) : "f"(f));
    return r;
}

__device__ __forceinline__ void mma_tf32(float& d0, float& d1, float& d2, float& d3,
                                         uint32_t a0, uint32_t a1, uint32_t a2, uint32_t a3,
                                         uint32_t b0, uint32_t b1) {
    asm volatile("mma.sync.aligned.m16n8k8.row.col.f32.tf32.tf32.f32 "
                 "{%0,%1,%2,%3}, {%4,%5,%6,%7}, {%8,%9}, {%0,%1,%2,%3};"
                 : "+f"(d0), "+f"(d1), "+f"(d2), "+f"(d3)
                 : "r"(a0), "r"(a1), "r"(a2), "r"(a3), "r"(b0), "r"(b1));
}

constexpr int WPB = 4;            // warps per block
constexpr int THREADS = WPB * 32;
constexpr int RPC = 16;           // regions per chunk (=> 80 H-rows = 5 MMA M-tiles)
constexpr int ROWS = RPC * 5;     // 80
constexpr int HS = 36;            // padded H row stride (floats): bank = 4r+c, conflict-free

// select component idx (0..27) from a float4[7] array with compile-time idx
#define WEL(idx) ((idx & 3) == 0 ? w4[(idx) >> 2].x : \
                  (idx & 3) == 1 ? w4[(idx) >> 2].y : \
                  (idx & 3) == 2 ? w4[(idx) >> 2].z : w4[(idx) >> 2].w)

__global__ __launch_bounds__(THREADS, 4)
void seir_kernel(const float* __restrict__ A, const float* __restrict__ Ap,
                 const float* __restrict__ x, const float* __restrict__ fcw,
                 const float* __restrict__ fcb, float* __restrict__ out,
                 int n_regions)
{
    __shared__ uint32_t shH[WPB][ROWS * HS];   // tf32 bits of H, fragment-friendly
    __shared__ float    shW[WPB][32];          // per-region W = A .* Ap broadcast buffer

    const int warp = threadIdx.x >> 5;
    const int lane = threadIdx.x & 31;
    const int g = lane >> 2;      // mma group id (row within octet)
    const int t = lane & 3;       // thread-in-group (col quartet)

    uint32_t* Hp = shH[warp];
    float*    Wp = shW[warp];

    const float a_l = (lane < 25) ? A[lane] : 0.0f;

    // ---- preload B fragments: B[k][n] = fcw[n][k], tf32, col-major frag ----
    uint32_t bf[4][4][2];   // [n-tile][k-step][reg]
#pragma unroll
    for (int nt = 0; nt < 4; nt++)
#pragma unroll
        for (int ks = 0; ks < 4; ks++) {
            const float* wr = fcw + (nt * 8 + g) * 32 + ks * 8 + t;
            bf[nt][ks][0] = f2tf32(wr[0]);
            bf[nt][ks][1] = f2tf32(wr[4]);
        }
    float blo[4], bhi[4];
#pragma unroll
    for (int nt = 0; nt < 4; nt++) {
        blo[nt] = fcb[nt * 8 + 2 * t];
        bhi[nt] = fcb[nt * 8 + 2 * t + 1];
    }

    const int total_chunks = (n_regions + RPC - 1) / RPC;
    const int gw = blockIdx.x * WPB + warp;
    const int nw = gridDim.x * WPB;
    const long long nrows = (long long)n_regions * 5;

    for (int ch = gw; ch < total_chunks; ch += nw) {
        const int n0 = ch * RPC;

        // ================= producer: h rows -> shared (tf32) =================
#pragma unroll 2
        for (int r = 0; r < RPC; r++) {
            const int n = n0 + r;
            const bool valid = (n < n_regions);

            float wv = 0.0f;
            if (valid && lane < 25) wv = a_l * Ap[(long long)n * 25 + lane];
            Wp[lane] = wv;
            __syncwarp();

            float4 w4[7];
#pragma unroll
            for (int k = 0; k < 7; k++) w4[k] = ((const float4*)Wp)[k];

            float xj[5];
            const float* xp = x + (long long)n * 160 + lane;
#pragma unroll
            for (int j = 0; j < 5; j++) xj[j] = valid ? xp[j * 32] : 0.0f;

#pragma unroll
            for (int i = 0; i < 5; i++) {
                float h =        WEL(i * 5 + 0) * xj[0];
                h = fmaf(WEL(i * 5 + 1), xj[1], h);
                h = fmaf(WEL(i * 5 + 2), xj[2], h);
                h = fmaf(WEL(i * 5 + 3), xj[3], h);
                h = fmaf(WEL(i * 5 + 4), xj[4], h);
                Hp[(r * 5 + i) * HS + lane] = f2tf32(h);
            }
            __syncwarp();   // protect Wp WAR for next region
        }
        __syncwarp();       // H visible across lanes

        // ================= consumer: tensor-core fc + relu =================
#pragma unroll
        for (int m = 0; m < 5; m++) {
            float acc[4][4];
#pragma unroll
            for (int nt = 0; nt < 4; nt++) {
                acc[nt][0] = blo[nt]; acc[nt][1] = bhi[nt];
                acc[nt][2] = blo[nt]; acc[nt][3] = bhi[nt];
            }
#pragma unroll
            for (int ks = 0; ks < 4; ks++) {
                const int base = (m * 16 + g) * HS + ks * 8 + t;
                uint32_t a0 = Hp[base];
                uint32_t a2 = Hp[base + 4];
                uint32_t a1 = Hp[base + 8 * HS];
                uint32_t a3 = Hp[base + 8 * HS + 4];
#pragma unroll
                for (int nt = 0; nt < 4; nt++)
                    mma_tf32(acc[nt][0], acc[nt][1], acc[nt][2], acc[nt][3],
                             a0, a1, a2, a3, bf[nt][ks][0], bf[nt][ks][1]);
            }
            const long long row0 = (long long)ch * ROWS + m * 16 + g;
#pragma unroll
            for (int nt = 0; nt < 4; nt++) {
                const int col = nt * 8 + 2 * t;
                if (row0 < nrows) {
                    float2 v = make_float2(fmaxf(acc[nt][0], 0.0f),
                                           fmaxf(acc[nt][1], 0.0f));
                    *(float2*)(out + row0 * 32 + col) = v;
                }
                if (row0 + 8 < nrows) {
                    float2 v = make_float2(fmaxf(acc[nt][2], 0.0f),
                                           fmaxf(acc[nt][3], 0.0f));
                    *(float2*)(out + (row0 + 8) * 32 + col) = v;
                }
            }
        }
        __syncwarp();       // consumer done reading Hp before next chunk
    }
}

extern "C" void kernel_launch(void* const* d_in, const int* in_sizes, int n_in,
                              void* d_out, int out_size)
{
    const float* A   = (const float*)d_in[0];
    const float* Ap  = (const float*)d_in[1];
    const float* x   = (const float*)d_in[2];
    const float* fcw = (const float*)d_in[3];
    const float* fcb = (const float*)d_in[4];
    float* out = (float*)d_out;

    const int n_regions = in_sizes[1] / 25;

    const int blocks = 148 * 4;   // grid-stride over chunks
    seir_kernel<<<blocks, THREADS>>>(A, Ap, x, fcw, fcb, out, n_regions);
}

// round 5
// speedup vs baseline: 1.5697x; 1.1157x over previous
#include <cuda_runtime.h>
#include <cstdint>

// seir_base: out[n,i,o] = relu( sum_c (sum_j A[i,j]*Ap[n,i,j]*x[n,j,c]) * fc_w[o,c] + fc_b[o] )
// R3: block-cooperative. 1 block = 4 warps = 16 regions. Shared H tile per BLOCK.
// Producer: exact fp32 h, warp lane = channel. Consumer: mma.sync m16n8k8 tf32,
// warp w owns output-column tile w (B-frags only 8 regs/thread).

__device__ __forceinline__ uint32_t f2tf32(float f) {
    uint32_t r;
    asm("cvt.rna.tf32.f32 %0, %1;" : "=r"(r) : "f"(f));
    return r;
}

__device__ __forceinline__ void mma_tf32(float& d0, float& d1, float& d2, float& d3,
                                         uint32_t a0, uint32_t a1, uint32_t a2, uint32_t a3,
                                         uint32_t b0, uint32_t b1) {
    asm volatile("mma.sync.aligned.m16n8k8.row.col.f32.tf32.tf32.f32 "
                 "{%0,%1,%2,%3}, {%4,%5,%6,%7}, {%8,%9}, {%0,%1,%2,%3};"
                 : "+f"(d0), "+f"(d1), "+f"(d2), "+f"(d3)
                 : "r"(a0), "r"(a1), "r"(a2), "r"(a3), "r"(b0), "r"(b1));
}

constexpr int THREADS = 128;
constexpr int RPC = 16;          // regions per block
constexpr int ROWS = RPC * 5;    // 80 H rows = 5 MMA m-tiles
constexpr int HS = 36;           // padded row stride: bank = 4g+t, conflict-free frags

// component select from float4[7] with compile-time idx 0..24
#define WEL(idx) ((idx & 3) == 0 ? w4[(idx) >> 2].x : \
                  (idx & 3) == 1 ? w4[(idx) >> 2].y : \
                  (idx & 3) == 2 ? w4[(idx) >> 2].z : w4[(idx) >> 2].w)

__global__ __launch_bounds__(THREADS, 8)
void seir_kernel(const float* __restrict__ A, const float* __restrict__ Ap,
                 const float* __restrict__ x, const float* __restrict__ fcw,
                 const float* __restrict__ fcb, float* __restrict__ out,
                 int n_regions)
{
    __shared__ uint32_t shH[ROWS * HS];   // tf32 bits of H (whole block)
    __shared__ float    shW[4][32];       // per-warp W broadcast buffer

    const int warp = threadIdx.x >> 5;
    const int lane = threadIdx.x & 31;
    const int g = lane >> 2;              // mma row-in-octet
    const int t = lane & 3;               // mma col quartet

    const float a_l = (lane < 25) ? A[lane] : 0.0f;

    // ---- B fragments for THIS warp's column tile (nt = warp) ----
    uint32_t bf[4][2];
#pragma unroll
    for (int ks = 0; ks < 4; ks++) {
        const float* wr = fcw + (warp * 8 + g) * 32 + ks * 8 + t;
        bf[ks][0] = f2tf32(wr[0]);
        bf[ks][1] = f2tf32(wr[4]);
    }
    const float blo = fcb[warp * 8 + 2 * t];
    const float bhi = fcb[warp * 8 + 2 * t + 1];

    const long long n0 = (long long)blockIdx.x * RPC + warp * 4;
    float* Wp = shW[warp];

    // ================= producer: 4 regions per warp, pipelined =================
    float ap_cur = 0.0f, xc[5];
    {
        const long long n = n0;
        const bool v = (n < n_regions);
        if (v && lane < 25) ap_cur = Ap[n * 25 + lane];
        const float* xp = x + n * 160 + lane;
#pragma unroll
        for (int j = 0; j < 5; j++) xc[j] = v ? xp[j * 32] : 0.0f;
    }

#pragma unroll
    for (int r = 0; r < 4; r++) {
        // prefetch next region
        float ap_nx = 0.0f, xn[5];
        if (r < 3) {
            const long long n = n0 + r + 1;
            const bool v = (n < n_regions);
            if (v && lane < 25) ap_nx = Ap[n * 25 + lane];
            const float* xp = x + n * 160 + lane;
#pragma unroll
            for (int j = 0; j < 5; j++) xn[j] = v ? xp[j * 32] : 0.0f;
        }

        Wp[lane] = a_l * ap_cur;
        __syncwarp();
        float4 w4[7];
#pragma unroll
        for (int k = 0; k < 7; k++) w4[k] = ((const float4*)Wp)[k];

        const int row0 = (warp * 4 + r) * 5;
#pragma unroll
        for (int i = 0; i < 5; i++) {
            float h =        WEL(i * 5 + 0) * xc[0];
            h = fmaf(WEL(i * 5 + 1), xc[1], h);
            h = fmaf(WEL(i * 5 + 2), xc[2], h);
            h = fmaf(WEL(i * 5 + 3), xc[3], h);
            h = fmaf(WEL(i * 5 + 4), xc[4], h);
            shH[(row0 + i) * HS + lane] = f2tf32(h);
        }
        __syncwarp();   // Wp WAR protection

        ap_cur = ap_nx;
#pragma unroll
        for (int j = 0; j < 5; j++) xc[j] = xn[j];
    }

    __syncthreads();

    // ================= consumer: warp w -> column tile w =================
    const long long nrows = (long long)n_regions * 5;
    const int col = warp * 8 + 2 * t;

#pragma unroll
    for (int m = 0; m < 5; m++) {
        float c0 = blo, c1 = bhi, c2 = blo, c3 = bhi;
#pragma unroll
        for (int ks = 0; ks < 4; ks++) {
            const int base = (m * 16 + g) * HS + ks * 8 + t;
            uint32_t a0 = shH[base];
            uint32_t a2 = shH[base + 4];
            uint32_t a1 = shH[base + 8 * HS];
            uint32_t a3 = shH[base + 8 * HS + 4];
            mma_tf32(c0, c1, c2, c3, a0, a1, a2, a3, bf[ks][0], bf[ks][1]);
        }
        const long long row0 = (long long)blockIdx.x * ROWS + m * 16 + g;
        if (row0 < nrows)
            *(float2*)(out + row0 * 32 + col) =
                make_float2(fmaxf(c0, 0.0f), fmaxf(c1, 0.0f));
        if (row0 + 8 < nrows)
            *(float2*)(out + (row0 + 8) * 32 + col) =
                make_float2(fmaxf(c2, 0.0f), fmaxf(c3, 0.0f));
    }
}

extern "C" void kernel_launch(void* const* d_in, const int* in_sizes, int n_in,
                              void* d_out, int out_size)
{
    const float* A   = (const float*)d_in[0];
    const float* Ap  = (const float*)d_in[1];
    const float* x   = (const float*)d_in[2];
    const float* fcw = (const float*)d_in[3];
    const float* fcb = (const float*)d_in[4];
    float* out = (float*)d_out;

    const int n_regions = in_sizes[1] / 25;
    const int blocks = (n_regions + RPC - 1) / RPC;

    seir_kernel<<<blocks, THREADS>>>(A, Ap, x, fcw, fcb, out, n_regions);
}